// round 3
// baseline (speedup 1.0000x reference)
#include <cuda_runtime.h>
#include <math.h>

#define BATCH 2
#define SEQ   2048
#define EMB   1024
#define NH    16
#define HD    64
#define NCATS 5

// Scratch: Q,K,V,attended in [B,H,S,D] layout. 4 x 16MB device globals.
__device__ float g_Q[BATCH*NH*SEQ*HD];
__device__ float g_K[BATCH*NH*SEQ*HD];
__device__ float g_V[BATCH*NH*SEQ*HD];
__device__ float g_att[BATCH*NH*SEQ*HD];

// ---------------------------------------------------------------------------
// Projection GEMM: C[M=4096][N=1024] = A(MxK) * W(NxK)^T + bias
// MODE 0: A read linear [m][k], C written remapped to [B,H,S,D]   (QKV proj)
// MODE 1: A read remapped from [B,H,S,D], C written linear [m][n] (O proj)
// 128x128 tile, BK=8, 256 threads, 8x8 micro-tile.
// ---------------------------------------------------------------------------
template<int MODE>
__global__ __launch_bounds__(256)
void proj_kernel(const float* __restrict__ A, const float* __restrict__ W,
                 const float* __restrict__ bias, float* __restrict__ C)
{
    __shared__ float As[8][132];
    __shared__ float Ws[8][132];

    const int tid = threadIdx.x;
    const int tm  = tid >> 4;        // 0..15
    const int tn  = tid & 15;        // 0..15
    const int m0  = blockIdx.y * 128;
    const int n0  = blockIdx.x * 128;

    const int lr = tid >> 1;         // 0..127 (tile row for load)
    const int lk = (tid & 1) * 4;    // 0 or 4  (k offset within BK=8)

    float acc[8][8];
    #pragma unroll
    for (int i = 0; i < 8; i++)
        #pragma unroll
        for (int j = 0; j < 8; j++) acc[i][j] = 0.f;

    for (int k0 = 0; k0 < EMB; k0 += 8) {
        float4 av;
        if (MODE == 0) {
            av = *(const float4*)(A + (size_t)(m0 + lr) * EMB + k0 + lk);
        } else {
            const int m = m0 + lr;
            const int b = m >> 11, s = m & 2047;
            const int k = k0 + lk;
            const int h = k >> 6, d = k & 63;
            av = *(const float4*)(A + ((size_t)((b*NH + h)*SEQ + s))*HD + d);
        }
        As[lk+0][lr] = av.x; As[lk+1][lr] = av.y;
        As[lk+2][lr] = av.z; As[lk+3][lr] = av.w;

        float4 wv = *(const float4*)(W + (size_t)(n0 + lr) * EMB + k0 + lk);
        Ws[lk+0][lr] = wv.x; Ws[lk+1][lr] = wv.y;
        Ws[lk+2][lr] = wv.z; Ws[lk+3][lr] = wv.w;

        __syncthreads();

        #pragma unroll
        for (int kk = 0; kk < 8; kk++) {
            float a[8], w[8];
            *(float4*)(a)     = *(const float4*)&As[kk][tm*8];
            *(float4*)(a + 4) = *(const float4*)&As[kk][tm*8 + 4];
            *(float4*)(w)     = *(const float4*)&Ws[kk][tn*8];
            *(float4*)(w + 4) = *(const float4*)&Ws[kk][tn*8 + 4];
            #pragma unroll
            for (int i = 0; i < 8; i++)
                #pragma unroll
                for (int j = 0; j < 8; j++)
                    acc[i][j] += a[i] * w[j];
        }
        __syncthreads();
    }

    #pragma unroll
    for (int i = 0; i < 8; i++) {
        const int m = m0 + tm*8 + i;
        #pragma unroll
        for (int j4 = 0; j4 < 8; j4 += 4) {
            const int n = n0 + tn*8 + j4;
            float4 r;
            r.x = acc[i][j4+0] + bias[n+0];
            r.y = acc[i][j4+1] + bias[n+1];
            r.z = acc[i][j4+2] + bias[n+2];
            r.w = acc[i][j4+3] + bias[n+3];
            if (MODE == 0) {
                const int b = m >> 11, s = m & 2047;
                const int h = n >> 6, d = n & 63;
                *(float4*)(C + ((size_t)((b*NH + h)*SEQ + s))*HD + d) = r;
            } else {
                *(float4*)(C + (size_t)m * EMB + n) = r;
            }
        }
    }
}

// ---------------------------------------------------------------------------
// Flash attention: one CTA per (b, h, 64-row q tile). 256 threads = 16x16,
// 4x4 micro-tiles. Q^T/K^T stored d-major in smem for outer-product QK.
// Online softmax with shuffle reductions over the 16-lane row groups.
// ---------------------------------------------------------------------------
#define TPAD 68                       // row stride (floats) in smem tiles
#define ATTN_SMEM_BYTES (((4*64*TPAD + 32) * 4) + 128*4)   // 70272 B

__global__ __launch_bounds__(256)
void attn_kernel(const int* __restrict__ responses, const int* __restrict__ mask,
                 const float* __restrict__ Wm, const float* __restrict__ bm)
{
    extern __shared__ float smem[];
    float* QsT = smem;                  // [64 d][TPAD] : QsT[d*TPAD + r] = Q[r][d] * invscale
    float* KsT = smem + 64*TPAD;        // [64 d][TPAD] : KsT[d*TPAD + j] = K[j][d]
    float* Vs  = smem + 2*64*TPAD;      // [64 j][TPAD] : Vs[j*TPAD + c]  = V[j][c]
    float* Ps  = smem + 3*64*TPAD;      // [64 r][TPAD] : exp'd scores
    float* tbl = smem + 4*64*TPAD;      // 25 entries: qwk[a][c]*Wm[h] + bm[h]
    int*   rq  = (int*)(tbl + 32);      // 64
    int*   rk  = rq + 64;               // 64

    const int tid = threadIdx.x;
    const int tm  = tid >> 4;           // row group 0..15 -> rows tm*4..+3
    const int tn  = tid & 15;           // col group 0..15 -> cols tn*4..+3
    const int qb = blockIdx.x, h = blockIdx.y, b = blockIdx.z;
    const int q0 = qb * 64;
    const float invscale = 0.125f;      // 1/sqrt(64)

    if (tid < 25) {
        const int a = tid / 5, c = tid % 5;
        const float dq = (float)(a - c);
        tbl[tid] = (1.0f - dq*dq * (1.0f/16.0f)) * Wm[h] + bm[h];
    }
    if (tid < 64) rq[tid] = responses[b*SEQ + q0 + tid];

    const float* Qg = g_Q + ((size_t)(b*NH + h)*SEQ + q0)*HD;
    const float* Kg = g_K + ((size_t)(b*NH + h)*SEQ)*HD;
    const float* Vg = g_V + ((size_t)(b*NH + h)*SEQ)*HD;
    const int*   Mb = mask + (size_t)b*SEQ*SEQ;

    // Load Q tile transposed (pre-scaled)
    for (int e = tid; e < 1024; e += 256) {       // 1024 float4 = 64x64
        const int r = e >> 4, c4 = (e & 15) * 4;
        float4 v = *(const float4*)(Qg + r*HD + c4);
        QsT[(c4+0)*TPAD + r] = v.x * invscale;
        QsT[(c4+1)*TPAD + r] = v.y * invscale;
        QsT[(c4+2)*TPAD + r] = v.z * invscale;
        QsT[(c4+3)*TPAD + r] = v.w * invscale;
    }
    __syncthreads();

    int rqr[4];
    #pragma unroll
    for (int rr = 0; rr < 4; rr++) rqr[rr] = rq[tm*4 + rr];

    float m_i[4], l_i[4], Oacc[4][4];
    #pragma unroll
    for (int rr = 0; rr < 4; rr++) {
        m_i[rr] = -1e30f; l_i[rr] = 0.f;
        #pragma unroll
        for (int cc = 0; cc < 4; cc++) Oacc[rr][cc] = 0.f;
    }

    for (int kb = 0; kb < SEQ/64; kb++) {
        const int k0 = kb * 64;

        // Load K tile transposed + V tile natural
        for (int e = tid; e < 1024; e += 256) {
            const int r = e >> 4, c4 = (e & 15) * 4;
            float4 kv = *(const float4*)(Kg + (k0 + r)*HD + c4);
            KsT[(c4+0)*TPAD + r] = kv.x;
            KsT[(c4+1)*TPAD + r] = kv.y;
            KsT[(c4+2)*TPAD + r] = kv.z;
            KsT[(c4+3)*TPAD + r] = kv.w;
            float4 vv = *(const float4*)(Vg + (k0 + r)*HD + c4);
            *(float4*)(Vs + r*TPAD + c4) = vv;
        }
        if (tid < 64) rk[tid] = responses[b*SEQ + k0 + tid];
        __syncthreads();

        // ---- scores: S[r][j] = Q[r].K[j] (Q pre-scaled) ----
        float sc[4][4];
        #pragma unroll
        for (int rr = 0; rr < 4; rr++)
            #pragma unroll
            for (int jj = 0; jj < 4; jj++) sc[rr][jj] = 0.f;

        #pragma unroll 16
        for (int d = 0; d < 64; d++) {
            float4 qa = *(const float4*)(QsT + d*TPAD + tm*4);
            float4 ka = *(const float4*)(KsT + d*TPAD + tn*4);
            const float qv[4] = {qa.x, qa.y, qa.z, qa.w};
            const float kv[4] = {ka.x, ka.y, ka.z, ka.w};
            #pragma unroll
            for (int rr = 0; rr < 4; rr++)
                #pragma unroll
                for (int jj = 0; jj < 4; jj++)
                    sc[rr][jj] += qv[rr] * kv[jj];
        }

        // ---- bias + mask ----
        int rkr[4];
        #pragma unroll
        for (int jj = 0; jj < 4; jj++) rkr[jj] = rk[tn*4 + jj];
        #pragma unroll
        for (int rr = 0; rr < 4; rr++) {
            const float* tr = tbl + rqr[rr]*5;
            int4 mv = *(const int4*)(Mb + (size_t)(q0 + tm*4 + rr)*SEQ + k0 + tn*4);
            sc[rr][0] = (mv.x == 0) ? -1e9f : sc[rr][0] + tr[rkr[0]];
            sc[rr][1] = (mv.y == 0) ? -1e9f : sc[rr][1] + tr[rkr[1]];
            sc[rr][2] = (mv.z == 0) ? -1e9f : sc[rr][2] + tr[rkr[2]];
            sc[rr][3] = (mv.w == 0) ? -1e9f : sc[rr][3] + tr[rkr[3]];
        }

        // ---- online softmax, write P to smem ----
        #pragma unroll
        for (int rr = 0; rr < 4; rr++) {
            float mx = fmaxf(fmaxf(sc[rr][0], sc[rr][1]), fmaxf(sc[rr][2], sc[rr][3]));
            mx = fmaxf(mx, __shfl_xor_sync(0xffffffffu, mx, 8));
            mx = fmaxf(mx, __shfl_xor_sync(0xffffffffu, mx, 4));
            mx = fmaxf(mx, __shfl_xor_sync(0xffffffffu, mx, 2));
            mx = fmaxf(mx, __shfl_xor_sync(0xffffffffu, mx, 1));
            const float mnew  = fmaxf(m_i[rr], mx);
            const float alpha = __expf(m_i[rr] - mnew);
            m_i[rr] = mnew;
            float rs = 0.f;
            #pragma unroll
            for (int jj = 0; jj < 4; jj++) {
                const float p = __expf(sc[rr][jj] - mnew);
                sc[rr][jj] = p;
                rs += p;
            }
            rs += __shfl_xor_sync(0xffffffffu, rs, 8);
            rs += __shfl_xor_sync(0xffffffffu, rs, 4);
            rs += __shfl_xor_sync(0xffffffffu, rs, 2);
            rs += __shfl_xor_sync(0xffffffffu, rs, 1);
            l_i[rr] = l_i[rr] * alpha + rs;
            #pragma unroll
            for (int cc = 0; cc < 4; cc++) Oacc[rr][cc] *= alpha;
            *(float4*)(Ps + (tm*4 + rr)*TPAD + tn*4) = *(float4*)sc[rr];
        }
        __syncthreads();

        // ---- O += P @ V ----
        #pragma unroll 8
        for (int j = 0; j < 64; j++) {
            float4 vv = *(const float4*)(Vs + j*TPAD + tn*4);
            const float vc[4] = {vv.x, vv.y, vv.z, vv.w};
            float pr[4];
            #pragma unroll
            for (int rr = 0; rr < 4; rr++) pr[rr] = Ps[(tm*4 + rr)*TPAD + j];
            #pragma unroll
            for (int rr = 0; rr < 4; rr++)
                #pragma unroll
                for (int cc = 0; cc < 4; cc++)
                    Oacc[rr][cc] += pr[rr] * vc[cc];
        }
        __syncthreads();
    }

    // ---- epilogue: normalize + store to g_att [B,H,S,D] ----
    float* Og = g_att + ((size_t)(b*NH + h)*SEQ + q0)*HD;
    #pragma unroll
    for (int rr = 0; rr < 4; rr++) {
        const float inv = 1.0f / l_i[rr];
        float4 r;
        r.x = Oacc[rr][0] * inv;
        r.y = Oacc[rr][1] * inv;
        r.z = Oacc[rr][2] * inv;
        r.w = Oacc[rr][3] * inv;
        *(float4*)(Og + (tm*4 + rr)*HD + tn*4) = r;
    }
}

// ---------------------------------------------------------------------------
extern "C" void kernel_launch(void* const* d_in, const int* in_sizes, int n_in,
                              void* d_out, int out_size)
{
    const float* query     = (const float*)d_in[0];
    const float* key_      = (const float*)d_in[1];
    const float* value     = (const float*)d_in[2];
    const int*   responses = (const int*)  d_in[3];
    const int*   mask      = (const int*)  d_in[4];
    const float* Wq = (const float*)d_in[5];
    const float* bq = (const float*)d_in[6];
    const float* Wk = (const float*)d_in[7];
    const float* bk = (const float*)d_in[8];
    const float* Wv = (const float*)d_in[9];
    const float* bv = (const float*)d_in[10];
    const float* Wo = (const float*)d_in[11];
    const float* bo = (const float*)d_in[12];
    const float* Wm = (const float*)d_in[13];
    const float* bmv = (const float*)d_in[14];
    float* out = (float*)d_out;

    float *qp, *kp, *vp, *ap;
    cudaGetSymbolAddress((void**)&qp, g_Q);
    cudaGetSymbolAddress((void**)&kp, g_K);
    cudaGetSymbolAddress((void**)&vp, g_V);
    cudaGetSymbolAddress((void**)&ap, g_att);

    dim3 pgrid(EMB/128, (BATCH*SEQ)/128);   // (8, 32)
    proj_kernel<0><<<pgrid, 256>>>(query, Wq, bq, qp);
    proj_kernel<0><<<pgrid, 256>>>(key_,  Wk, bk, kp);
    proj_kernel<0><<<pgrid, 256>>>(value, Wv, bv, vp);

    cudaFuncSetAttribute(attn_kernel, cudaFuncAttributeMaxDynamicSharedMemorySize,
                         ATTN_SMEM_BYTES);
    dim3 agrid(SEQ/64, NH, BATCH);          // (32, 16, 2)
    attn_kernel<<<agrid, 256, ATTN_SMEM_BYTES>>>(responses, mask, Wm, bmv);

    proj_kernel<1><<<pgrid, 256>>>(ap, Wo, bo, out);
}